// round 13
// baseline (speedup 1.0000x reference)
#include <cuda_runtime.h>
#include <cuda_bf16.h>
#include <math.h>
#include <stdint.h>

#define NN   10000
#define FIN  3000
#define HH1  500
#define HH2  64
#define NE   160000
#define KP_FIN 3008
#define KP_H1  512
#define KP_N   10048
#define NP_W1  512
#define NP_DEC 9216
#define NSEG   3072

static const long long Z1_OFF   = 0LL;
static const long long PI_OFF   = 1920000LL;
static const long long REC_OFF  = 91920000LL;
static const long long RET_OFF  = 191920000LL;

__device__ float g_S   [NN * HH1];
__device__ float g_H   [NN * HH1];
__device__ float g_S2  [NN * HH2];
__device__ float g_EMB1[NN * HH2];
__device__ float g_EMB3[NN * HH2];
__device__ float g_VSUM[NN * HH2];
__device__ float g_G2  [NN * HH2];
__device__ float g_RSUM[NN];
__device__ float g_BNA [HH1];
__device__ float g_BNB [HH1];
__device__ float g_BCAT[NP_DEC];
__device__ __nv_bfloat16 g_Ah[(size_t)NN * KP_FIN];
__device__ __nv_bfloat16 g_Al[(size_t)NN * KP_FIN];
__device__ __nv_bfloat16 g_W1th[(size_t)NP_W1 * KP_FIN];
__device__ __nv_bfloat16 g_W1tl[(size_t)NP_W1 * KP_FIN];
__device__ __nv_bfloat16 g_XDh[(size_t)NN * KP_H1];
__device__ __nv_bfloat16 g_XDl[(size_t)NN * KP_H1];
__device__ __nv_bfloat16 g_Wcth[(size_t)NP_DEC * KP_H1];
__device__ __nv_bfloat16 g_Wctl[(size_t)NP_DEC * KP_H1];
__device__ __nv_bfloat16 g_Gh[(size_t)NN * KP_N];
__device__ __nv_bfloat16 g_E1th[(size_t)64 * KP_N];
__device__ __nv_bfloat16 g_E1tl[(size_t)64 * KP_N];
__device__ __nv_bfloat16 g_ZNh[(size_t)NN * 64];
__device__ __nv_bfloat16 g_ZNl[(size_t)NN * 64];
__device__ int g_cnt[NN];
__device__ int g_start[NN + 1];
__device__ int g_pos[NN];
__device__ int g_eidx[NE];

// ---------------- helpers ----------------
__device__ __forceinline__ uint32_t smem_u32(const void* p) {
    uint32_t a;
    asm("{ .reg .u64 t; cvta.to.shared.u64 t, %1; cvt.u32.u64 %0, t; }" : "=r"(a) : "l"(p));
    return a;
}
__device__ __forceinline__ void cpa16(uint32_t saddr, const void* g, bool pred) {
    int sz = pred ? 16 : 0;
    asm volatile("cp.async.cg.shared.global [%0], [%1], 16, %2;" :: "r"(saddr), "l"(g), "r"(sz) : "memory");
}
__device__ __forceinline__ void ldsm4(uint32_t* r, uint32_t addr) {
    asm volatile("ldmatrix.sync.aligned.m8n8.x4.shared.b16 {%0,%1,%2,%3}, [%4];"
        : "=r"(r[0]), "=r"(r[1]), "=r"(r[2]), "=r"(r[3]) : "r"(addr));
}
__device__ __forceinline__ void mma16816(float* d, const uint32_t* a, const uint32_t* b) {
    asm volatile(
        "mma.sync.aligned.m16n8k16.row.col.f32.bf16.bf16.f32 "
        "{%0,%1,%2,%3}, {%4,%5,%6,%7}, {%8,%9}, {%0,%1,%2,%3};"
        : "+f"(d[0]), "+f"(d[1]), "+f"(d[2]), "+f"(d[3])
        : "r"(a[0]), "r"(a[1]), "r"(a[2]), "r"(a[3]), "r"(b[0]), "r"(b[1]));
}

// EPI: 0 none, 6 poly-sigmoid [-1,1], 7 decoder segmented epilogue
template<int EPI>
__device__ __forceinline__ void epi_store(float v, float* __restrict__ C, int ldc,
                                          int r, int gc, int M, int Nreal,
                                          const float* __restrict__ bias, int splitk)
{
    if (r >= M) return;
    if (EPI == 7) {
        int seg = gc / NSEG;
        int cl = gc - seg * NSEG;
        if (cl >= FIN) return;
        float x = v + bias[gc];
        float o;
        if (seg == 0) {
            o = 1.f / (1.f + expf(-x));
        } else if (seg == 1) {
            float sp = (x > 0.f) ? x + log1pf(expf(-x)) : log1pf(expf(x));
            o = fminf(fmaxf(sp, 1e-4f), 1e4f);
        } else {
            o = fminf(fmaxf(expf(x), 1e-5f), 1e6f);
        }
        C[(size_t)seg * ((size_t)NN * FIN) + (size_t)r * FIN + cl] = o;
        return;
    }
    if (gc >= Nreal) return;
    float o = v;
    if (EPI == 6) {
        float u = v * v;
        float p = fmaf(u, 2.1357286e-5f, -2.1084563e-4f);
        p = fmaf(u, p, 2.0833334e-3f);
        p = fmaf(u, p, -2.0833333e-2f);
        p = fmaf(u, p, 0.25f);
        o = fmaf(v, p, 0.5f);
    }
    if (splitk > 1) atomicAdd(&C[(size_t)r * ldc + gc], o);
    else C[(size_t)r * ldc + gc] = o;
}

// ============================================================
// bf16-split mma.sync GEMM, ldmatrix + 2-stage cp.async, BK=64.
// 64KB smem -> 2 CTAs/SM (inter-CTA latency hiding).
// ============================================================
template<int BN, int EPI, int NPASS, int DUALB, int SPLITK>
__global__ void __launch_bounds__(256, 2) gemm_mma(
    const __nv_bfloat16* __restrict__ Ah, const __nv_bfloat16* __restrict__ Al, int lda,
    const __nv_bfloat16* __restrict__ Bh, const __nv_bfloat16* __restrict__ Bl, int ldb, int NB,
    float* __restrict__ C, int ldc, int M, int Nreal, int Kp,
    const float* __restrict__ bias)
{
    constexpr int WN = BN / 4;
    constexpr int NT = WN / 8;
    constexpr int ASTR = 128 * 128;
    constexpr int BSUB = BN * 128;
    constexpr int BSTR = BSUB * (1 + DUALB);
    constexpr int BBASE = 2 * ASTR;
    extern __shared__ __align__(16) char dsm[];
    const uint32_t smem = smem_u32(dsm);

    const int tid = threadIdx.x;
    const int wid = tid >> 5, lane = tid & 31;
    const int wm = wid >> 2, wn = wid & 3;
    const int row0 = blockIdx.y * 128, col0 = blockIdx.x * BN;

    const __nv_bfloat16* APP[3] = {Ah, Ah, Al};
    const __nv_bfloat16* BPP[3] = {Bh, Bl, Bh};

    const int KTtot = Kp >> 6;
    int k_begin = 0, k_count = KTtot;
    if (SPLITK > 1) {
        int half = (KTtot + SPLITK - 1) / SPLITK;
        k_begin = blockIdx.z * half;
        k_count = min(KTtot - k_begin, half);
    }
    const int S = k_count * NPASS;

    float acc[4][NT][4];
    #pragma unroll
    for (int i = 0; i < 4; i++)
        #pragma unroll
        for (int j = 0; j < NT; j++)
            #pragma unroll
            for (int k = 0; k < 4; k++) acc[i][j][k] = 0.f;

    auto load_stage = [&](int s) {
        const int buf = s & 1;
        const int pass = s / k_count;
        const int k0 = (k_begin + (s - pass * k_count)) << 6;
        const __nv_bfloat16* Ap = APP[pass];
        #pragma unroll
        for (int g = tid; g < 1024; g += 256) {
            int r = g >> 3, c = g & 7;
            int gr = row0 + r;
            bool p = (gr < M); if (!p) gr = 0;
            uint32_t sa = smem + buf * ASTR + r * 128 + ((c ^ (r & 7)) << 4);
            cpa16(sa, Ap + (size_t)gr * lda + k0 + c * 8, p);
        }
        const __nv_bfloat16* Bp = BPP[pass];
        #pragma unroll
        for (int g = tid; g < BN * 8; g += 256) {
            int r = g >> 3, c = g & 7;
            int gn = col0 + r;
            bool p = (gn < NB); if (!p) gn = 0;
            uint32_t sa = smem + BBASE + buf * BSTR + r * 128 + ((c ^ (r & 7)) << 4);
            cpa16(sa, Bp + (size_t)gn * ldb + k0 + c * 8, p);
        }
        if (DUALB) {
            #pragma unroll
            for (int g = tid; g < BN * 8; g += 256) {
                int r = g >> 3, c = g & 7;
                int gn = col0 + r;
                bool p = (gn < NB); if (!p) gn = 0;
                uint32_t sa = smem + BBASE + buf * BSTR + BSUB + r * 128 + ((c ^ (r & 7)) << 4);
                cpa16(sa, Bl + (size_t)gn * ldb + k0 + c * 8, p);
            }
        }
        asm volatile("cp.async.commit_group;" ::: "memory");
    };

    const int swz = lane & 7;
    const int rA = (lane & 7) + (((lane >> 3) & 1) << 3);
    const int hiA = lane >> 4;
    const int rB = (lane & 7) + (((lane >> 4) & 1) << 3);
    const int hiB = (lane >> 3) & 1;

    load_stage(0);
    if (S > 1) load_stage(1);

    for (int s = 0; s < S; s++) {
        if (s + 1 < S) { asm volatile("cp.async.wait_group 1;" ::: "memory"); }
        else           { asm volatile("cp.async.wait_group 0;" ::: "memory"); }
        __syncthreads();

        const int buf = s & 1;
        const uint32_t aBase = smem + buf * ASTR + (wm * 64 + rA) * 128;
        const uint32_t bBase = smem + BBASE + buf * BSTR + (wn * WN + rB) * 128;

        #pragma unroll
        for (int kk = 0; kk < 4; kk++) {
            uint32_t af[4][4];
            const uint32_t aoff = (((kk * 2 + hiA) ^ swz) << 4);
            #pragma unroll
            for (int mi = 0; mi < 4; mi++)
                ldsm4(af[mi], aBase + mi * 2048 + aoff);
            const uint32_t boff = (((kk * 2 + hiB) ^ swz) << 4);
            uint32_t bf[NT][2];
            #pragma unroll
            for (int np = 0; np < NT / 2; np++) {
                uint32_t t4[4];
                ldsm4(t4, bBase + np * 2048 + boff);
                bf[np * 2][0] = t4[0]; bf[np * 2][1] = t4[1];
                bf[np * 2 + 1][0] = t4[2]; bf[np * 2 + 1][1] = t4[3];
            }
            #pragma unroll
            for (int mi = 0; mi < 4; mi++)
                #pragma unroll
                for (int ni = 0; ni < NT; ni++)
                    mma16816(acc[mi][ni], af[mi], bf[ni]);
            if (DUALB) {
                uint32_t bl[NT][2];
                #pragma unroll
                for (int np = 0; np < NT / 2; np++) {
                    uint32_t t4[4];
                    ldsm4(t4, bBase + BSUB + np * 2048 + boff);
                    bl[np * 2][0] = t4[0]; bl[np * 2][1] = t4[1];
                    bl[np * 2 + 1][0] = t4[2]; bl[np * 2 + 1][1] = t4[3];
                }
                #pragma unroll
                for (int mi = 0; mi < 4; mi++)
                    #pragma unroll
                    for (int ni = 0; ni < NT; ni++)
                        mma16816(acc[mi][ni], af[mi], bl[ni]);
            }
        }
        __syncthreads();
        if (s + 2 < S) load_stage(s + 2);
    }

    #pragma unroll
    for (int mi = 0; mi < 4; mi++) {
        #pragma unroll
        for (int ni = 0; ni < NT; ni++) {
            int gr = row0 + wm * 64 + mi * 16 + (lane >> 2);
            int gc = col0 + wn * WN + ni * 8 + (lane & 3) * 2;
            #pragma unroll
            for (int h = 0; h < 2; h++) {
                int r = gr + h * 8;
                epi_store<EPI>(acc[mi][ni][2 * h], C, ldc, r, gc, M, Nreal, bias, SPLITK);
                epi_store<EPI>(acc[mi][ni][2 * h + 1], C, ldc, r, gc + 1, M, Nreal, bias, SPLITK);
            }
        }
    }
}

// ---------------- conversions (vectorized) ----------------
__global__ void conv_rows(const float* __restrict__ in, int K, int Kp,
                          __nv_bfloat16* __restrict__ hi, __nv_bfloat16* __restrict__ lo,
                          float* __restrict__ rsum)
{
    const int r = blockIdx.x;
    const float4* src4 = (const float4*)(in + (size_t)r * K);
    const int K4 = K >> 2, Kp4 = Kp >> 2;
    const size_t o = (size_t)r * Kp;
    float s = 0.f;
    for (int c4 = threadIdx.x; c4 < Kp4; c4 += 256) {
        float4 v = (c4 < K4) ? src4[c4] : make_float4(0.f, 0.f, 0.f, 0.f);
        s += (v.x + v.y) + (v.z + v.w);
        __nv_bfloat16 h0 = __float2bfloat16(v.x), h1 = __float2bfloat16(v.y);
        __nv_bfloat16 h2 = __float2bfloat16(v.z), h3 = __float2bfloat16(v.w);
        __nv_bfloat162* hp = (__nv_bfloat162*)(hi + o + 4 * c4);
        hp[0] = __nv_bfloat162{h0, h1};
        hp[1] = __nv_bfloat162{h2, h3};
        if (lo) {
            __nv_bfloat162* lp = (__nv_bfloat162*)(lo + o + 4 * c4);
            lp[0] = __nv_bfloat162{__float2bfloat16(v.x - __bfloat162float(h0)),
                                   __float2bfloat16(v.y - __bfloat162float(h1))};
            lp[1] = __nv_bfloat162{__float2bfloat16(v.z - __bfloat162float(h2)),
                                   __float2bfloat16(v.w - __bfloat162float(h3))};
        }
    }
    if (rsum) {
        __shared__ float red[256];
        red[threadIdx.x] = s; __syncthreads();
        for (int st = 128; st > 0; st >>= 1) {
            if (threadIdx.x < st) red[threadIdx.x] += red[threadIdx.x + st];
            __syncthreads();
        }
        if (threadIdx.x == 0) rsum[r] = red[0];
    }
}
__global__ void conv_transpose(const float* __restrict__ W, int K, int N, int Kp, int Np,
                               __nv_bfloat16* __restrict__ hi, __nv_bfloat16* __restrict__ lo,
                               int do_relu)
{
    long long idx = (long long)blockIdx.x * blockDim.x + threadIdx.x;
    if (idx >= (long long)Np * Kp) return;
    int n = (int)(idx / Kp), k = (int)(idx % Kp);
    float v = (n < N && k < K) ? W[(size_t)k * N + n] : 0.f;
    if (do_relu) v = fmaxf(v, 0.f);
    __nv_bfloat16 h = __float2bfloat16(v);
    hi[idx] = h;
    lo[idx] = __float2bfloat16(v - __bfloat162float(h));
}
__global__ void znconv_kernel(const float* __restrict__ z1,
                              __nv_bfloat16* __restrict__ hi, __nv_bfloat16* __restrict__ lo, int M)
{
    int gw = (blockIdx.x * blockDim.x + threadIdx.x) >> 5;
    int lane = threadIdx.x & 31;
    if (gw >= M) return;
    float x0 = z1[(size_t)gw * 64 + lane];
    float x1 = z1[(size_t)gw * 64 + 32 + lane];
    float ss = x0 * x0 + x1 * x1;
    #pragma unroll
    for (int o = 16; o > 0; o >>= 1) ss += __shfl_xor_sync(0xffffffffu, ss, o);
    float d = fmaxf(sqrtf(ss), 1e-12f);
    float v0 = x0 / d, v1 = x1 / d;
    __nv_bfloat16 h0 = __float2bfloat16(v0), h1 = __float2bfloat16(v1);
    hi[(size_t)gw * 64 + lane] = h0;
    hi[(size_t)gw * 64 + 32 + lane] = h1;
    lo[(size_t)gw * 64 + lane] = __float2bfloat16(v0 - __bfloat162float(h0));
    lo[(size_t)gw * 64 + 32 + lane] = __float2bfloat16(v1 - __bfloat162float(h1));
}
__global__ void biascat_kernel(const float* __restrict__ bpi, const float* __restrict__ bdisp,
                               const float* __restrict__ bmean, float* __restrict__ bcat)
{
    int idx = blockIdx.x * blockDim.x + threadIdx.x;
    if (idx >= NP_DEC) return;
    int seg = idx / NSEG, cl = idx - seg * NSEG;
    float v = 0.f;
    if (cl < FIN) v = (seg == 0) ? bpi[cl] : (seg == 1) ? bdisp[cl] : bmean[cl];
    bcat[idx] = v;
}

// ---------------- CSR build + aggregation ----------------
__global__ void zero_int_kernel(int* __restrict__ p, int n) {
    int i = blockIdx.x * blockDim.x + threadIdx.x;
    if (i < n) p[i] = 0;
}
__global__ void hist_kernel(const int* __restrict__ rows, int* __restrict__ cnt) {
    int e = blockIdx.x * blockDim.x + threadIdx.x;
    if (e < NE) atomicAdd(&cnt[rows[e]], 1);
}
__global__ void scan_kernel(const int* __restrict__ cnt, int* __restrict__ start,
                            int* __restrict__ pos, int n)
{
    __shared__ int part[1024];
    const int tid = threadIdx.x;
    const int per = (n + 1023) / 1024;
    const int b0 = tid * per;
    int s = 0;
    for (int i = 0; i < per; i++) { int j = b0 + i; if (j < n) s += cnt[j]; }
    part[tid] = s; __syncthreads();
    for (int off = 1; off < 1024; off <<= 1) {
        int v = (tid >= off) ? part[tid - off] : 0;
        __syncthreads();
        part[tid] += v;
        __syncthreads();
    }
    int excl = (tid == 0) ? 0 : part[tid - 1];
    for (int i = 0; i < per; i++) {
        int j = b0 + i;
        if (j < n) { start[j] = excl; pos[j] = excl; excl += cnt[j]; }
    }
    if (tid == 1023) start[n] = part[1023];
}
__global__ void scatter_kernel(const int* __restrict__ rows, int* __restrict__ pos,
                               int* __restrict__ eidx)
{
    int e = blockIdx.x * blockDim.x + threadIdx.x;
    if (e >= NE) return;
    int p = atomicAdd(&pos[rows[e]], 1);
    eidx[p] = e;
}
__global__ void agg_csr_500(const int* __restrict__ start, const int* __restrict__ eidx,
                            const int* __restrict__ cols, const float* __restrict__ vals,
                            const float* __restrict__ S, float* __restrict__ out)
{
    const int r = blockIdx.x;
    const int b = start[r], e = start[r + 1];
    const int t = threadIdx.x;
    float a0 = 0.f, a1 = 0.f;
    for (int i = b; i < e; i++) {
        int ed = __ldg(&eidx[i]);
        int c = __ldg(&cols[ed]);
        float v = __ldg(&vals[ed]);
        const float* src = S + (size_t)c * HH1;
        a0 += v * __ldg(&src[t]);
        if (t + 256 < HH1) a1 += v * __ldg(&src[t + 256]);
    }
    a0 = fmaxf(a0, 0.f); a1 = fmaxf(a1, 0.f);
    float* dst = out + (size_t)r * HH1;
    dst[t] = a0;
    if (t + 256 < HH1) dst[t + 256] = a1;
}
__global__ void agg_csr_64(const int* __restrict__ start, const int* __restrict__ eidx,
                           const int* __restrict__ cols, const float* __restrict__ vals,
                           const float* __restrict__ S, float* __restrict__ out,
                           float* __restrict__ Eout)
{
    const int r = blockIdx.x * 4 + (threadIdx.x >> 6);
    const int c64 = threadIdx.x & 63;
    if (r >= NN) return;
    const int b = start[r], e = start[r + 1];
    float a = 0.f;
    for (int i = b; i < e; i++) {
        int ed = __ldg(&eidx[i]);
        a += __ldg(&vals[ed]) * __ldg(&S[(size_t)__ldg(&cols[ed]) * HH2 + c64]);
    }
    out[(size_t)r * HH2 + c64] = a;
    if (Eout) Eout[(size_t)r * HH2 + c64] = fmaxf(a, 0.f);
}

// ---------------- fp32 small GEMMs ----------------
__global__ void sgemm0_kernel(const float* __restrict__ A, const float* __restrict__ B,
                              float* __restrict__ C, int M, int N, int K)
{
    __shared__ float As[64][17];
    __shared__ float Bs[16][64];
    const int tx = threadIdx.x, ty = threadIdx.y;
    const int tid = ty * 16 + tx;
    const int row0 = blockIdx.y * 64, col0 = blockIdx.x * 64;
    float acc[4][4];
    #pragma unroll
    for (int i = 0; i < 4; i++)
        #pragma unroll
        for (int j = 0; j < 4; j++) acc[i][j] = 0.f;
    const int nt = (K + 15) / 16;
    for (int t = 0; t < nt; t++) {
        const int k0 = t * 16;
        #pragma unroll
        for (int p = 0; p < 4; p++) {
            int i = (tid >> 4) + p * 16, kk = tid & 15;
            int ar = row0 + i, ak = k0 + kk;
            As[i][kk] = (ar < M && ak < K) ? A[(size_t)ar * K + ak] : 0.f;
        }
        #pragma unroll
        for (int p = 0; p < 4; p++) {
            int kk = (tid >> 6) + p * 4, j = tid & 63;
            int bk = k0 + kk, bc = col0 + j;
            Bs[kk][j] = (bk < K && bc < N) ? B[(size_t)bk * N + bc] : 0.f;
        }
        __syncthreads();
        #pragma unroll
        for (int kk = 0; kk < 16; kk++) {
            float a[4];
            #pragma unroll
            for (int i = 0; i < 4; i++) a[i] = As[ty * 4 + i][kk];
            float4 b4 = *reinterpret_cast<const float4*>(&Bs[kk][tx * 4]);
            float b[4] = {b4.x, b4.y, b4.z, b4.w};
            #pragma unroll
            for (int i = 0; i < 4; i++)
                #pragma unroll
                for (int j = 0; j < 4; j++)
                    acc[i][j] = fmaf(a[i], b[j], acc[i][j]);
        }
        __syncthreads();
    }
    #pragma unroll
    for (int i = 0; i < 4; i++) {
        int row = row0 + ty * 4 + i;
        if (row >= M) continue;
        #pragma unroll
        for (int j = 0; j < 4; j++) {
            int col = col0 + tx * 4 + j;
            if (col >= N) continue;
            C[(size_t)row * N + col] = acc[i][j];
        }
    }
}
__global__ void sgemm_xd_kernel(const float* __restrict__ A, const float* __restrict__ B,
                                __nv_bfloat16* __restrict__ Chi, __nv_bfloat16* __restrict__ Clo,
                                int M, int N, int K,
                                const float* __restrict__ scl, const float* __restrict__ bias)
{
    __shared__ float As[64][17];
    __shared__ float Bs[16][64];
    const int tx = threadIdx.x, ty = threadIdx.y;
    const int tid = ty * 16 + tx;
    const int row0 = blockIdx.y * 64, col0 = blockIdx.x * 64;
    float acc[4][4];
    #pragma unroll
    for (int i = 0; i < 4; i++)
        #pragma unroll
        for (int j = 0; j < 4; j++) acc[i][j] = 0.f;
    const int nt = (K + 15) / 16;
    for (int t = 0; t < nt; t++) {
        const int k0 = t * 16;
        #pragma unroll
        for (int p = 0; p < 4; p++) {
            int i = (tid >> 4) + p * 16, kk = tid & 15;
            int ar = row0 + i, ak = k0 + kk;
            As[i][kk] = (ar < M && ak < K) ? A[(size_t)ar * K + ak] : 0.f;
        }
        #pragma unroll
        for (int p = 0; p < 4; p++) {
            int kk = (tid >> 6) + p * 4, j = tid & 63;
            int bk = k0 + kk, bc = col0 + j;
            Bs[kk][j] = (bk < K && bc < N) ? B[(size_t)bk * N + bc] : 0.f;
        }
        __syncthreads();
        #pragma unroll
        for (int kk = 0; kk < 16; kk++) {
            float a[4];
            #pragma unroll
            for (int i = 0; i < 4; i++) a[i] = As[ty * 4 + i][kk];
            float4 b4 = *reinterpret_cast<const float4*>(&Bs[kk][tx * 4]);
            float b[4] = {b4.x, b4.y, b4.z, b4.w};
            #pragma unroll
            for (int i = 0; i < 4; i++)
                #pragma unroll
                for (int j = 0; j < 4; j++)
                    acc[i][j] = fmaf(a[i], b[j], acc[i][j]);
        }
        __syncthreads();
    }
    #pragma unroll
    for (int i = 0; i < 4; i++) {
        int row = row0 + ty * 4 + i;
        if (row >= M) continue;
        #pragma unroll
        for (int j = 0; j < 4; j++) {
            int col = col0 + tx * 4 + j;
            if (col >= N) continue;
            float v = fmaxf(fmaf(scl[col], acc[i][j], bias[col]), 0.f);
            __nv_bfloat16 h = __float2bfloat16(v);
            Chi[(size_t)row * KP_H1 + col] = h;
            Clo[(size_t)row * KP_H1 + col] = __float2bfloat16(v - __bfloat162float(h));
        }
    }
}

// ---------------- misc ----------------
__global__ void zero_kernel(float4* __restrict__ p, long long n4)
{
    long long i = (long long)blockIdx.x * blockDim.x + threadIdx.x;
    if (i < n4) p[i] = make_float4(0.f, 0.f, 0.f, 0.f);
}
__global__ void bnprep_kernel(const float* __restrict__ gamma, const float* __restrict__ beta,
                              const float* __restrict__ mean, const float* __restrict__ var,
                              const float* __restrict__ bd, float* __restrict__ a, float* __restrict__ b)
{
    int j = blockIdx.x * blockDim.x + threadIdx.x;
    if (j >= HH1) return;
    float s = gamma[j] * rsqrtf(var[j] + 1e-5f);
    a[j] = s;
    b[j] = beta[j] + s * (bd[j] - mean[j]);
}
__global__ void g2_kernel(const float* __restrict__ vsum, const float* __restrict__ rsum,
                          float* __restrict__ g2, int M)
{
    int gw = (blockIdx.x * blockDim.x + threadIdx.x) >> 5;
    int lane = threadIdx.x & 31;
    if (gw >= M) return;
    float inv = 1.f / rsum[gw];
    float x0 = vsum[(size_t)gw * 64 + lane] * inv;
    float x1 = vsum[(size_t)gw * 64 + 32 + lane] * inv;
    float ss = x0 * x0 + x1 * x1;
    #pragma unroll
    for (int o = 16; o > 0; o >>= 1) ss += __shfl_xor_sync(0xffffffffu, ss, o);
    float d = fmaxf(sqrtf(ss), 1e-12f);
    g2[(size_t)gw * 64 + lane] = 1.f / (1.f + expf(-x0 / d));
    g2[(size_t)gw * 64 + 32 + lane] = 1.f / (1.f + expf(-x1 / d));
}
__global__ void disc_kernel(const float* __restrict__ emb1, const float* __restrict__ emb3,
                            const float* __restrict__ g2, const float* __restrict__ W,
                            const float* __restrict__ bptr, float* __restrict__ ret, int M)
{
    __shared__ float Ws[64][65];
    int tid = threadIdx.x;
    for (int id = tid; id < 4096; id += 256) Ws[id >> 6][id & 63] = W[id];
    __syncthreads();
    int lane = tid & 31;
    int row = blockIdx.x * 8 + (tid >> 5);
    if (row >= M) return;
    float g0 = g2[(size_t)row * 64 + lane];
    float g1 = g2[(size_t)row * 64 + 32 + lane];
    float ulo = 0.f, uhi = 0.f;
    #pragma unroll
    for (int e = 0; e < 64; e++) {
        float ge = (e < 32) ? __shfl_sync(0xffffffffu, g0, e) : __shfl_sync(0xffffffffu, g1, e - 32);
        ulo = fmaf(Ws[lane][e], ge, ulo);
        uhi = fmaf(Ws[lane + 32][e], ge, uhi);
    }
    float s1 = emb1[(size_t)row * 64 + lane] * ulo + emb1[(size_t)row * 64 + 32 + lane] * uhi;
    float s2 = emb3[(size_t)row * 64 + lane] * ulo + emb3[(size_t)row * 64 + 32 + lane] * uhi;
    #pragma unroll
    for (int o = 16; o > 0; o >>= 1) {
        s1 += __shfl_xor_sync(0xffffffffu, s1, o);
        s2 += __shfl_xor_sync(0xffffffffu, s2, o);
    }
    if (lane == 0) {
        float b = bptr[0];
        ret[(size_t)row * 2 + 0] = s1 + b;
        ret[(size_t)row * 2 + 1] = s2 + b;
    }
}

static inline int cdiv(int a, int b) { return (a + b - 1) / b; }

extern "C" void kernel_launch(void* const* d_in, const int* in_sizes, int n_in,
                              void* d_out, int out_size)
{
    const float* feat   = (const float*)d_in[0];
    const float* feat_a = (const float*)d_in[1];
    const float* feat_b = (const float*)d_in[2];
    const int* adj_rows = (const int*)d_in[3];
    const int* adj_cols = (const int*)d_in[4];
    const float* adj_vals = (const float*)d_in[5];
    const float* graphN = (const float*)d_in[6];
    const float* W1 = (const float*)d_in[7];
    const float* W2 = (const float*)d_in[8];
    const float* Wd = (const float*)d_in[9];
    const float* bd = (const float*)d_in[10];
    const float* bn_gamma = (const float*)d_in[11];
    const float* bn_beta  = (const float*)d_in[12];
    const float* bn_mean  = (const float*)d_in[13];
    const float* bn_var   = (const float*)d_in[14];
    const float* Wpi   = (const float*)d_in[15];
    const float* bpi   = (const float*)d_in[16];
    const float* Wdisp = (const float*)d_in[17];
    const float* bdisp = (const float*)d_in[18];
    const float* Wmean = (const float*)d_in[19];
    const float* bmean = (const float*)d_in[20];
    const float* disc_W = (const float*)d_in[21];
    const float* disc_b = (const float*)d_in[22];
    float* out = (float*)d_out;

    #define SYM(T, v, s) T* v; { void* p_; cudaGetSymbolAddress(&p_, s); v = (T*)p_; }
    SYM(float, S, g_S)  SYM(float, H, g_H)  SYM(float, S2, g_S2)
    SYM(float, E1, g_EMB1) SYM(float, E3, g_EMB3) SYM(float, VS, g_VSUM) SYM(float, G2v, g_G2)
    SYM(float, RS, g_RSUM) SYM(float, BA, g_BNA) SYM(float, BB, g_BNB) SYM(float, BCAT, g_BCAT)
    SYM(__nv_bfloat16, Ah, g_Ah) SYM(__nv_bfloat16, Al, g_Al)
    SYM(__nv_bfloat16, W1th, g_W1th) SYM(__nv_bfloat16, W1tl, g_W1tl)
    SYM(__nv_bfloat16, XDh, g_XDh) SYM(__nv_bfloat16, XDl, g_XDl)
    SYM(__nv_bfloat16, Wcth, g_Wcth) SYM(__nv_bfloat16, Wctl, g_Wctl)
    SYM(__nv_bfloat16, Gh, g_Gh) SYM(__nv_bfloat16, E1th, g_E1th) SYM(__nv_bfloat16, E1tl, g_E1tl)
    SYM(__nv_bfloat16, ZNh, g_ZNh) SYM(__nv_bfloat16, ZNl, g_ZNl)
    SYM(int, CNT, g_cnt) SYM(int, START, g_start) SYM(int, POS, g_pos) SYM(int, EIDX, g_eidx)

    const int SM128 = 64 * 1024;   // 2*(16K A + 16K B)
    const int SM64D = 64 * 1024;   // 2*(16K A + 16K Bdual)
    cudaFuncSetAttribute(gemm_mma<128,0,3,0,1>, cudaFuncAttributeMaxDynamicSharedMemorySize, SM128);
    cudaFuncSetAttribute(gemm_mma<128,7,3,0,1>, cudaFuncAttributeMaxDynamicSharedMemorySize, SM128);
    cudaFuncSetAttribute(gemm_mma<128,6,3,0,1>, cudaFuncAttributeMaxDynamicSharedMemorySize, SM128);
    cudaFuncSetAttribute(gemm_mma<64,0,1,1,2>,  cudaFuncAttributeMaxDynamicSharedMemorySize, SM64D);

    const dim3 blk(16, 16);
    const int mt64 = cdiv(NN, 64), mt128 = cdiv(NN, 128);

    // CSR build
    zero_int_kernel<<<cdiv(NN, 256), 256>>>(CNT, NN);
    hist_kernel<<<cdiv(NE, 256), 256>>>(adj_rows, CNT);
    scan_kernel<<<1, 1024>>>(CNT, START, POS, NN);
    scatter_kernel<<<cdiv(NE, 256), 256>>>(adj_rows, POS, EIDX);

    // weight / bias conversions
    conv_transpose<<<(unsigned)(((long long)NP_W1 * KP_FIN + 255) / 256), 256>>>(W1, FIN, HH1, KP_FIN, NP_W1, W1th, W1tl, 0);
    conv_transpose<<<(unsigned)(((long long)NSEG * KP_H1 + 255) / 256), 256>>>(Wpi,   HH1, FIN, KP_H1, NSEG, Wcth,                        Wctl,                        0);
    conv_transpose<<<(unsigned)(((long long)NSEG * KP_H1 + 255) / 256), 256>>>(Wdisp, HH1, FIN, KP_H1, NSEG, Wcth + (size_t)NSEG*KP_H1,   Wctl + (size_t)NSEG*KP_H1,   0);
    conv_transpose<<<(unsigned)(((long long)NSEG * KP_H1 + 255) / 256), 256>>>(Wmean, HH1, FIN, KP_H1, NSEG, Wcth + (size_t)2*NSEG*KP_H1, Wctl + (size_t)2*NSEG*KP_H1, 0);
    biascat_kernel<<<cdiv(NP_DEC, 256), 256>>>(bpi, bdisp, bmean, BCAT);
    bnprep_kernel<<<cdiv(HH1, 256), 256>>>(bn_gamma, bn_beta, bn_mean, bn_var, bd, BA, BB);
    conv_rows<<<NN, 256>>>(graphN, NN, KP_N, Gh, nullptr, RS);

    // ---- encodes (per-encode, L2-friendly) ----
    const float* xs[3] = {feat, feat_a, feat_b};
    float* Eo[3] = {E1, nullptr, E3};
    for (int s = 0; s < 3; s++) {
        float* z = out + Z1_OFF + (long long)s * 640000LL;
        conv_rows<<<NN, 256>>>(xs[s], FIN, KP_FIN, Ah, Al, nullptr);
        gemm_mma<128,0,3,0,1><<<dim3(NP_W1 / 128, mt128), 256, SM128>>>(
            Ah, Al, KP_FIN, W1th, W1tl, KP_FIN, NP_W1, S, HH1, NN, HH1, KP_FIN, nullptr);
        agg_csr_500<<<NN, 256>>>(START, EIDX, adj_cols, adj_vals, S, H);
        sgemm0_kernel<<<dim3(1, mt64), blk>>>(H, W2, S2, NN, HH2, HH1);
        agg_csr_64<<<cdiv(NN, 4), 256>>>(START, EIDX, adj_cols, adj_vals, S2, z, Eo[s]);
    }
    float* z1 = out + Z1_OFF;

    // ---- ZINB decoder: fused single GEMM (N = 9216) ----
    sgemm_xd_kernel<<<dim3(cdiv(HH1, 64), mt64), blk>>>(z1, Wd, XDh, XDl, NN, HH1, HH2, BA, BB);
    gemm_mma<128,7,3,0,1><<<dim3(NP_DEC / 128, mt128), 256, SM128>>>(
        XDh, XDl, KP_H1, Wcth, Wctl, KP_H1, NP_DEC, out + PI_OFF, FIN, NN, NP_DEC, KP_H1, BCAT);

    // ---- rec_adj = poly-sigmoid(zn @ zn^T) ----
    znconv_kernel<<<cdiv(NN * 32, 256), 256>>>(z1, ZNh, ZNl, NN);
    gemm_mma<128,6,3,0,1><<<dim3(cdiv(NN, 128), mt128), 256, SM128>>>(
        ZNh, ZNl, 64, ZNh, ZNl, 64, NN, out + REC_OFF, NN, NN, NN, 64, nullptr);

    // ---- readout: single pass (dual-B) + split-K=2 ----
    conv_transpose<<<(unsigned)(((long long)64 * KP_N + 255) / 256), 256>>>(z1, NN, HH2, KP_N, 64, E1th, E1tl, 1);
    zero_kernel<<<cdiv(NN * HH2 / 4, 256), 256>>>((float4*)VS, (long long)NN * HH2 / 4);
    gemm_mma<64,0,1,1,2><<<dim3(1, mt128, 2), 256, SM64D>>>(
        Gh, nullptr, KP_N, E1th, E1tl, KP_N, 64, VS, HH2, NN, HH2, KP_N, nullptr);
    g2_kernel<<<cdiv(NN * 32, 256), 256>>>(VS, RS, G2v, NN);
    disc_kernel<<<cdiv(NN, 8), 256>>>(E1, E3, G2v, disc_W, disc_b, out + RET_OFF, NN);
}

// round 16
// speedup vs baseline: 1.4694x; 1.4694x over previous
#include <cuda_runtime.h>
#include <cuda_bf16.h>
#include <math.h>
#include <stdint.h>

#define NN   10000
#define FIN  3000
#define HH1  500
#define HH2  64
#define NE   160000
#define KP_FIN 3008
#define KP_H1  512
#define KP_N   10048
#define NP_W1  512
#define NP_DEC 9216
#define NSEG   3072

static const long long Z1_OFF   = 0LL;
static const long long PI_OFF   = 1920000LL;
static const long long REC_OFF  = 91920000LL;
static const long long RET_OFF  = 191920000LL;

__device__ float g_S   [NN * HH1];
__device__ float g_H   [NN * HH1];
__device__ float g_S2  [NN * HH2];
__device__ float g_EMB1[NN * HH2];
__device__ float g_EMB3[NN * HH2];
__device__ float g_VSUM[NN * HH2];
__device__ float g_G2  [NN * HH2];
__device__ float g_RSUM[NN];
__device__ float g_BNA [HH1];
__device__ float g_BNB [HH1];
__device__ float g_BCAT[NP_DEC];
__device__ __nv_bfloat16 g_Ah[(size_t)NN * KP_FIN];
__device__ __nv_bfloat16 g_Al[(size_t)NN * KP_FIN];
__device__ __nv_bfloat16 g_W1th[(size_t)NP_W1 * KP_FIN];
__device__ __nv_bfloat16 g_W1tl[(size_t)NP_W1 * KP_FIN];
__device__ __nv_bfloat16 g_XDh[(size_t)NN * KP_H1];
__device__ __nv_bfloat16 g_XDl[(size_t)NN * KP_H1];
__device__ __nv_bfloat16 g_Wcth[(size_t)NP_DEC * KP_H1];
__device__ __nv_bfloat16 g_Wctl[(size_t)NP_DEC * KP_H1];
__device__ __nv_bfloat16 g_Gh[(size_t)NN * KP_N];
__device__ __nv_bfloat16 g_E1th[(size_t)64 * KP_N];
__device__ __nv_bfloat16 g_E1tl[(size_t)64 * KP_N];
__device__ __nv_bfloat16 g_ZNh[(size_t)NN * 64];
__device__ __nv_bfloat16 g_ZNl[(size_t)NN * 64];
__device__ int g_cnt[NN];
__device__ int g_start[NN + 1];
__device__ int g_pos[NN];
__device__ int g_eidx[NE];

// ---------------- helpers ----------------
__device__ __forceinline__ uint32_t smem_u32(const void* p) {
    uint32_t a;
    asm("{ .reg .u64 t; cvta.to.shared.u64 t, %1; cvt.u32.u64 %0, t; }" : "=r"(a) : "l"(p));
    return a;
}
__device__ __forceinline__ void cpa16(uint32_t saddr, const void* g, bool pred) {
    int sz = pred ? 16 : 0;
    asm volatile("cp.async.cg.shared.global [%0], [%1], 16, %2;" :: "r"(saddr), "l"(g), "r"(sz) : "memory");
}
__device__ __forceinline__ void ldsm4(uint32_t* r, uint32_t addr) {
    asm volatile("ldmatrix.sync.aligned.m8n8.x4.shared.b16 {%0,%1,%2,%3}, [%4];"
        : "=r"(r[0]), "=r"(r[1]), "=r"(r[2]), "=r"(r[3]) : "r"(addr));
}
__device__ __forceinline__ void mma16816(float* d, const uint32_t* a, const uint32_t* b) {
    asm volatile(
        "mma.sync.aligned.m16n8k16.row.col.f32.bf16.bf16.f32 "
        "{%0,%1,%2,%3}, {%4,%5,%6,%7}, {%8,%9}, {%0,%1,%2,%3};"
        : "+f"(d[0]), "+f"(d[1]), "+f"(d[2]), "+f"(d[3])
        : "r"(a[0]), "r"(a[1]), "r"(a[2]), "r"(a[3]), "r"(b[0]), "r"(b[1]));
}

// EPI: 0 none, 6 poly-sigmoid [-1,1], 7 decoder segmented epilogue
template<int EPI>
__device__ __forceinline__ void epi_store(float v, float* __restrict__ C, int ldc,
                                          int r, int gc, int M, int Nreal,
                                          const float* __restrict__ bias, int splitk)
{
    if (r >= M) return;
    if (EPI == 7) {
        int seg = gc / NSEG;
        int cl = gc - seg * NSEG;
        if (cl >= FIN) return;
        float x = v + bias[gc];
        float o;
        if (seg == 0) {
            o = 1.f / (1.f + expf(-x));
        } else if (seg == 1) {
            float sp = (x > 0.f) ? x + log1pf(expf(-x)) : log1pf(expf(x));
            o = fminf(fmaxf(sp, 1e-4f), 1e4f);
        } else {
            o = fminf(fmaxf(expf(x), 1e-5f), 1e6f);
        }
        C[(size_t)seg * ((size_t)NN * FIN) + (size_t)r * FIN + cl] = o;
        return;
    }
    if (gc >= Nreal) return;
    float o = v;
    if (EPI == 6) {
        float u = v * v;
        float p = fmaf(u, 2.1357286e-5f, -2.1084563e-4f);
        p = fmaf(u, p, 2.0833334e-3f);
        p = fmaf(u, p, -2.0833333e-2f);
        p = fmaf(u, p, 0.25f);
        o = fmaf(v, p, 0.5f);
    }
    if (splitk > 1) atomicAdd(&C[(size_t)r * ldc + gc], o);
    else C[(size_t)r * ldc + gc] = o;
}

// ============================================================
// bf16-split mma.sync GEMM, ldmatrix + 3-stage cp.async, BK=64.
// (R11 configuration: 96KB smem, 1 CTA/SM, no reg cap.)
// ============================================================
template<int BN, int EPI, int NPASS, int DUALB, int SPLITK>
__global__ void __launch_bounds__(256) gemm_mma(
    const __nv_bfloat16* __restrict__ Ah, const __nv_bfloat16* __restrict__ Al, int lda,
    const __nv_bfloat16* __restrict__ Bh, const __nv_bfloat16* __restrict__ Bl, int ldb, int NB,
    float* __restrict__ C, int ldc, int M, int Nreal, int Kp,
    const float* __restrict__ bias)
{
    constexpr int WN = BN / 4;
    constexpr int NT = WN / 8;
    constexpr int ASTR = 128 * 128;
    constexpr int BSUB = BN * 128;
    constexpr int BSTR = BSUB * (1 + DUALB);
    constexpr int BBASE = 3 * ASTR;
    extern __shared__ __align__(16) char dsm[];
    const uint32_t smem = smem_u32(dsm);

    const int tid = threadIdx.x;
    const int wid = tid >> 5, lane = tid & 31;
    const int wm = wid >> 2, wn = wid & 3;
    const int row0 = blockIdx.y * 128, col0 = blockIdx.x * BN;

    const __nv_bfloat16* APP[3] = {Ah, Ah, Al};
    const __nv_bfloat16* BPP[3] = {Bh, Bl, Bh};

    const int KTtot = Kp >> 6;
    int k_begin = 0, k_count = KTtot;
    if (SPLITK > 1) {
        int half = (KTtot + SPLITK - 1) / SPLITK;
        k_begin = blockIdx.z * half;
        k_count = min(KTtot - k_begin, half);
    }
    const int S = k_count * NPASS;

    float acc[4][NT][4];
    #pragma unroll
    for (int i = 0; i < 4; i++)
        #pragma unroll
        for (int j = 0; j < NT; j++)
            #pragma unroll
            for (int k = 0; k < 4; k++) acc[i][j][k] = 0.f;

    auto load_stage = [&](int s) {
        const int buf = s % 3;
        const int pass = s / k_count;
        const int k0 = (k_begin + (s - pass * k_count)) << 6;
        const __nv_bfloat16* Ap = APP[pass];
        #pragma unroll
        for (int g = tid; g < 1024; g += 256) {
            int r = g >> 3, c = g & 7;
            int gr = row0 + r;
            bool p = (gr < M); if (!p) gr = 0;
            uint32_t sa = smem + buf * ASTR + r * 128 + ((c ^ (r & 7)) << 4);
            cpa16(sa, Ap + (size_t)gr * lda + k0 + c * 8, p);
        }
        const __nv_bfloat16* Bp = BPP[pass];
        #pragma unroll
        for (int g = tid; g < BN * 8; g += 256) {
            int r = g >> 3, c = g & 7;
            int gn = col0 + r;
            bool p = (gn < NB); if (!p) gn = 0;
            uint32_t sa = smem + BBASE + buf * BSTR + r * 128 + ((c ^ (r & 7)) << 4);
            cpa16(sa, Bp + (size_t)gn * ldb + k0 + c * 8, p);
        }
        if (DUALB) {
            #pragma unroll
            for (int g = tid; g < BN * 8; g += 256) {
                int r = g >> 3, c = g & 7;
                int gn = col0 + r;
                bool p = (gn < NB); if (!p) gn = 0;
                uint32_t sa = smem + BBASE + buf * BSTR + BSUB + r * 128 + ((c ^ (r & 7)) << 4);
                cpa16(sa, Bl + (size_t)gn * ldb + k0 + c * 8, p);
            }
        }
        asm volatile("cp.async.commit_group;" ::: "memory");
    };

    const int swz = lane & 7;
    const int rA = (lane & 7) + (((lane >> 3) & 1) << 3);
    const int hiA = lane >> 4;
    const int rB = (lane & 7) + (((lane >> 4) & 1) << 3);
    const int hiB = (lane >> 3) & 1;

    load_stage(0);
    if (S > 1) load_stage(1);

    for (int s = 0; s < S; s++) {
        if (s + 1 < S) { asm volatile("cp.async.wait_group 1;" ::: "memory"); }
        else           { asm volatile("cp.async.wait_group 0;" ::: "memory"); }
        __syncthreads();
        if (s + 2 < S) load_stage(s + 2);

        const int buf = s % 3;
        const uint32_t aBase = smem + buf * ASTR + (wm * 64 + rA) * 128;
        const uint32_t bBase = smem + BBASE + buf * BSTR + (wn * WN + rB) * 128;

        #pragma unroll
        for (int kk = 0; kk < 4; kk++) {
            uint32_t af[4][4];
            const uint32_t aoff = (((kk * 2 + hiA) ^ swz) << 4);
            #pragma unroll
            for (int mi = 0; mi < 4; mi++)
                ldsm4(af[mi], aBase + mi * 2048 + aoff);
            const uint32_t boff = (((kk * 2 + hiB) ^ swz) << 4);
            uint32_t bf[NT][2];
            #pragma unroll
            for (int np = 0; np < NT / 2; np++) {
                uint32_t t4[4];
                ldsm4(t4, bBase + np * 2048 + boff);
                bf[np * 2][0] = t4[0]; bf[np * 2][1] = t4[1];
                bf[np * 2 + 1][0] = t4[2]; bf[np * 2 + 1][1] = t4[3];
            }
            #pragma unroll
            for (int mi = 0; mi < 4; mi++)
                #pragma unroll
                for (int ni = 0; ni < NT; ni++)
                    mma16816(acc[mi][ni], af[mi], bf[ni]);
            if (DUALB) {
                uint32_t bl[NT][2];
                #pragma unroll
                for (int np = 0; np < NT / 2; np++) {
                    uint32_t t4[4];
                    ldsm4(t4, bBase + BSUB + np * 2048 + boff);
                    bl[np * 2][0] = t4[0]; bl[np * 2][1] = t4[1];
                    bl[np * 2 + 1][0] = t4[2]; bl[np * 2 + 1][1] = t4[3];
                }
                #pragma unroll
                for (int mi = 0; mi < 4; mi++)
                    #pragma unroll
                    for (int ni = 0; ni < NT; ni++)
                        mma16816(acc[mi][ni], af[mi], bl[ni]);
            }
        }
        __syncthreads();
    }

    #pragma unroll
    for (int mi = 0; mi < 4; mi++) {
        #pragma unroll
        for (int ni = 0; ni < NT; ni++) {
            int gr = row0 + wm * 64 + mi * 16 + (lane >> 2);
            int gc = col0 + wn * WN + ni * 8 + (lane & 3) * 2;
            #pragma unroll
            for (int h = 0; h < 2; h++) {
                int r = gr + h * 8;
                epi_store<EPI>(acc[mi][ni][2 * h], C, ldc, r, gc, M, Nreal, bias, SPLITK);
                epi_store<EPI>(acc[mi][ni][2 * h + 1], C, ldc, r, gc + 1, M, Nreal, bias, SPLITK);
            }
        }
    }
}

// ---------------- conversions (vectorized) ----------------
__global__ void conv_rows(const float* __restrict__ in, int K, int Kp,
                          __nv_bfloat16* __restrict__ hi, __nv_bfloat16* __restrict__ lo,
                          float* __restrict__ rsum)
{
    const int r = blockIdx.x;
    const float4* src4 = (const float4*)(in + (size_t)r * K);
    const int K4 = K >> 2, Kp4 = Kp >> 2;
    const size_t o = (size_t)r * Kp;
    float s = 0.f;
    for (int c4 = threadIdx.x; c4 < Kp4; c4 += 256) {
        float4 v = (c4 < K4) ? src4[c4] : make_float4(0.f, 0.f, 0.f, 0.f);
        s += (v.x + v.y) + (v.z + v.w);
        __nv_bfloat16 h0 = __float2bfloat16(v.x), h1 = __float2bfloat16(v.y);
        __nv_bfloat16 h2 = __float2bfloat16(v.z), h3 = __float2bfloat16(v.w);
        __nv_bfloat162* hp = (__nv_bfloat162*)(hi + o + 4 * c4);
        hp[0] = __nv_bfloat162{h0, h1};
        hp[1] = __nv_bfloat162{h2, h3};
        if (lo) {
            __nv_bfloat162* lp = (__nv_bfloat162*)(lo + o + 4 * c4);
            lp[0] = __nv_bfloat162{__float2bfloat16(v.x - __bfloat162float(h0)),
                                   __float2bfloat16(v.y - __bfloat162float(h1))};
            lp[1] = __nv_bfloat162{__float2bfloat16(v.z - __bfloat162float(h2)),
                                   __float2bfloat16(v.w - __bfloat162float(h3))};
        }
    }
    if (rsum) {
        __shared__ float red[256];
        red[threadIdx.x] = s; __syncthreads();
        for (int st = 128; st > 0; st >>= 1) {
            if (threadIdx.x < st) red[threadIdx.x] += red[threadIdx.x + st];
            __syncthreads();
        }
        if (threadIdx.x == 0) rsum[r] = red[0];
    }
}
__global__ void conv_transpose(const float* __restrict__ W, int K, int N, int Kp, int Np,
                               __nv_bfloat16* __restrict__ hi, __nv_bfloat16* __restrict__ lo,
                               int do_relu)
{
    long long idx = (long long)blockIdx.x * blockDim.x + threadIdx.x;
    if (idx >= (long long)Np * Kp) return;
    int n = (int)(idx / Kp), k = (int)(idx % Kp);
    float v = (n < N && k < K) ? W[(size_t)k * N + n] : 0.f;
    if (do_relu) v = fmaxf(v, 0.f);
    __nv_bfloat16 h = __float2bfloat16(v);
    hi[idx] = h;
    lo[idx] = __float2bfloat16(v - __bfloat162float(h));
}
__global__ void znconv_kernel(const float* __restrict__ z1,
                              __nv_bfloat16* __restrict__ hi, __nv_bfloat16* __restrict__ lo, int M)
{
    int gw = (blockIdx.x * blockDim.x + threadIdx.x) >> 5;
    int lane = threadIdx.x & 31;
    if (gw >= M) return;
    float x0 = z1[(size_t)gw * 64 + lane];
    float x1 = z1[(size_t)gw * 64 + 32 + lane];
    float ss = x0 * x0 + x1 * x1;
    #pragma unroll
    for (int o = 16; o > 0; o >>= 1) ss += __shfl_xor_sync(0xffffffffu, ss, o);
    float d = fmaxf(sqrtf(ss), 1e-12f);
    float v0 = x0 / d, v1 = x1 / d;
    __nv_bfloat16 h0 = __float2bfloat16(v0), h1 = __float2bfloat16(v1);
    hi[(size_t)gw * 64 + lane] = h0;
    hi[(size_t)gw * 64 + 32 + lane] = h1;
    lo[(size_t)gw * 64 + lane] = __float2bfloat16(v0 - __bfloat162float(h0));
    lo[(size_t)gw * 64 + 32 + lane] = __float2bfloat16(v1 - __bfloat162float(h1));
}
__global__ void biascat_kernel(const float* __restrict__ bpi, const float* __restrict__ bdisp,
                               const float* __restrict__ bmean, float* __restrict__ bcat)
{
    int idx = blockIdx.x * blockDim.x + threadIdx.x;
    if (idx >= NP_DEC) return;
    int seg = idx / NSEG, cl = idx - seg * NSEG;
    float v = 0.f;
    if (cl < FIN) v = (seg == 0) ? bpi[cl] : (seg == 1) ? bdisp[cl] : bmean[cl];
    bcat[idx] = v;
}

// ---------------- CSR build + aggregation ----------------
__global__ void zero_int_kernel(int* __restrict__ p, int n) {
    int i = blockIdx.x * blockDim.x + threadIdx.x;
    if (i < n) p[i] = 0;
}
__global__ void hist_kernel(const int* __restrict__ rows, int* __restrict__ cnt) {
    int e = blockIdx.x * blockDim.x + threadIdx.x;
    if (e < NE) atomicAdd(&cnt[rows[e]], 1);
}
__global__ void scan_kernel(const int* __restrict__ cnt, int* __restrict__ start,
                            int* __restrict__ pos, int n)
{
    __shared__ int part[1024];
    const int tid = threadIdx.x;
    const int per = (n + 1023) / 1024;
    const int b0 = tid * per;
    int s = 0;
    for (int i = 0; i < per; i++) { int j = b0 + i; if (j < n) s += cnt[j]; }
    part[tid] = s; __syncthreads();
    for (int off = 1; off < 1024; off <<= 1) {
        int v = (tid >= off) ? part[tid - off] : 0;
        __syncthreads();
        part[tid] += v;
        __syncthreads();
    }
    int excl = (tid == 0) ? 0 : part[tid - 1];
    for (int i = 0; i < per; i++) {
        int j = b0 + i;
        if (j < n) { start[j] = excl; pos[j] = excl; excl += cnt[j]; }
    }
    if (tid == 1023) start[n] = part[1023];
}
__global__ void scatter_kernel(const int* __restrict__ rows, int* __restrict__ pos,
                               int* __restrict__ eidx)
{
    int e = blockIdx.x * blockDim.x + threadIdx.x;
    if (e >= NE) return;
    int p = atomicAdd(&pos[rows[e]], 1);
    eidx[p] = e;
}
__global__ void agg_csr_500(const int* __restrict__ start, const int* __restrict__ eidx,
                            const int* __restrict__ cols, const float* __restrict__ vals,
                            const float* __restrict__ S, float* __restrict__ out)
{
    const int r = blockIdx.x;
    const int b = start[r], e = start[r + 1];
    const int t = threadIdx.x;
    float a0 = 0.f, a1 = 0.f;
    for (int i = b; i < e; i++) {
        int ed = __ldg(&eidx[i]);
        int c = __ldg(&cols[ed]);
        float v = __ldg(&vals[ed]);
        const float* src = S + (size_t)c * HH1;
        a0 += v * __ldg(&src[t]);
        if (t + 256 < HH1) a1 += v * __ldg(&src[t + 256]);
    }
    a0 = fmaxf(a0, 0.f); a1 = fmaxf(a1, 0.f);
    float* dst = out + (size_t)r * HH1;
    dst[t] = a0;
    if (t + 256 < HH1) dst[t + 256] = a1;
}
__global__ void agg_csr_64(const int* __restrict__ start, const int* __restrict__ eidx,
                           const int* __restrict__ cols, const float* __restrict__ vals,
                           const float* __restrict__ S, float* __restrict__ out,
                           float* __restrict__ Eout)
{
    const int r = blockIdx.x * 4 + (threadIdx.x >> 6);
    const int c64 = threadIdx.x & 63;
    if (r >= NN) return;
    const int b = start[r], e = start[r + 1];
    float a = 0.f;
    for (int i = b; i < e; i++) {
        int ed = __ldg(&eidx[i]);
        a += __ldg(&vals[ed]) * __ldg(&S[(size_t)__ldg(&cols[ed]) * HH2 + c64]);
    }
    out[(size_t)r * HH2 + c64] = a;
    if (Eout) Eout[(size_t)r * HH2 + c64] = fmaxf(a, 0.f);
}

// ---------------- fp32 small GEMMs ----------------
__global__ void sgemm0_kernel(const float* __restrict__ A, const float* __restrict__ B,
                              float* __restrict__ C, int M, int N, int K)
{
    __shared__ float As[64][17];
    __shared__ float Bs[16][64];
    const int tx = threadIdx.x, ty = threadIdx.y;
    const int tid = ty * 16 + tx;
    const int row0 = blockIdx.y * 64, col0 = blockIdx.x * 64;
    float acc[4][4];
    #pragma unroll
    for (int i = 0; i < 4; i++)
        #pragma unroll
        for (int j = 0; j < 4; j++) acc[i][j] = 0.f;
    const int nt = (K + 15) / 16;
    for (int t = 0; t < nt; t++) {
        const int k0 = t * 16;
        #pragma unroll
        for (int p = 0; p < 4; p++) {
            int i = (tid >> 4) + p * 16, kk = tid & 15;
            int ar = row0 + i, ak = k0 + kk;
            As[i][kk] = (ar < M && ak < K) ? A[(size_t)ar * K + ak] : 0.f;
        }
        #pragma unroll
        for (int p = 0; p < 4; p++) {
            int kk = (tid >> 6) + p * 4, j = tid & 63;
            int bk = k0 + kk, bc = col0 + j;
            Bs[kk][j] = (bk < K && bc < N) ? B[(size_t)bk * N + bc] : 0.f;
        }
        __syncthreads();
        #pragma unroll
        for (int kk = 0; kk < 16; kk++) {
            float a[4];
            #pragma unroll
            for (int i = 0; i < 4; i++) a[i] = As[ty * 4 + i][kk];
            float4 b4 = *reinterpret_cast<const float4*>(&Bs[kk][tx * 4]);
            float b[4] = {b4.x, b4.y, b4.z, b4.w};
            #pragma unroll
            for (int i = 0; i < 4; i++)
                #pragma unroll
                for (int j = 0; j < 4; j++)
                    acc[i][j] = fmaf(a[i], b[j], acc[i][j]);
        }
        __syncthreads();
    }
    #pragma unroll
    for (int i = 0; i < 4; i++) {
        int row = row0 + ty * 4 + i;
        if (row >= M) continue;
        #pragma unroll
        for (int j = 0; j < 4; j++) {
            int col = col0 + tx * 4 + j;
            if (col >= N) continue;
            C[(size_t)row * N + col] = acc[i][j];
        }
    }
}
__global__ void sgemm_xd_kernel(const float* __restrict__ A, const float* __restrict__ B,
                                __nv_bfloat16* __restrict__ Chi, __nv_bfloat16* __restrict__ Clo,
                                int M, int N, int K,
                                const float* __restrict__ scl, const float* __restrict__ bias)
{
    __shared__ float As[64][17];
    __shared__ float Bs[16][64];
    const int tx = threadIdx.x, ty = threadIdx.y;
    const int tid = ty * 16 + tx;
    const int row0 = blockIdx.y * 64, col0 = blockIdx.x * 64;
    float acc[4][4];
    #pragma unroll
    for (int i = 0; i < 4; i++)
        #pragma unroll
        for (int j = 0; j < 4; j++) acc[i][j] = 0.f;
    const int nt = (K + 15) / 16;
    for (int t = 0; t < nt; t++) {
        const int k0 = t * 16;
        #pragma unroll
        for (int p = 0; p < 4; p++) {
            int i = (tid >> 4) + p * 16, kk = tid & 15;
            int ar = row0 + i, ak = k0 + kk;
            As[i][kk] = (ar < M && ak < K) ? A[(size_t)ar * K + ak] : 0.f;
        }
        #pragma unroll
        for (int p = 0; p < 4; p++) {
            int kk = (tid >> 6) + p * 4, j = tid & 63;
            int bk = k0 + kk, bc = col0 + j;
            Bs[kk][j] = (bk < K && bc < N) ? B[(size_t)bk * N + bc] : 0.f;
        }
        __syncthreads();
        #pragma unroll
        for (int kk = 0; kk < 16; kk++) {
            float a[4];
            #pragma unroll
            for (int i = 0; i < 4; i++) a[i] = As[ty * 4 + i][kk];
            float4 b4 = *reinterpret_cast<const float4*>(&Bs[kk][tx * 4]);
            float b[4] = {b4.x, b4.y, b4.z, b4.w};
            #pragma unroll
            for (int i = 0; i < 4; i++)
                #pragma unroll
                for (int j = 0; j < 4; j++)
                    acc[i][j] = fmaf(a[i], b[j], acc[i][j]);
        }
        __syncthreads();
    }
    #pragma unroll
    for (int i = 0; i < 4; i++) {
        int row = row0 + ty * 4 + i;
        if (row >= M) continue;
        #pragma unroll
        for (int j = 0; j < 4; j++) {
            int col = col0 + tx * 4 + j;
            if (col >= N) continue;
            float v = fmaxf(fmaf(scl[col], acc[i][j], bias[col]), 0.f);
            __nv_bfloat16 h = __float2bfloat16(v);
            Chi[(size_t)row * KP_H1 + col] = h;
            Clo[(size_t)row * KP_H1 + col] = __float2bfloat16(v - __bfloat162float(h));
        }
    }
}

// ---------------- misc ----------------
__global__ void zero_kernel(float4* __restrict__ p, long long n4)
{
    long long i = (long long)blockIdx.x * blockDim.x + threadIdx.x;
    if (i < n4) p[i] = make_float4(0.f, 0.f, 0.f, 0.f);
}
__global__ void bnprep_kernel(const float* __restrict__ gamma, const float* __restrict__ beta,
                              const float* __restrict__ mean, const float* __restrict__ var,
                              const float* __restrict__ bd, float* __restrict__ a, float* __restrict__ b)
{
    int j = blockIdx.x * blockDim.x + threadIdx.x;
    if (j >= HH1) return;
    float s = gamma[j] * rsqrtf(var[j] + 1e-5f);
    a[j] = s;
    b[j] = beta[j] + s * (bd[j] - mean[j]);
}
__global__ void g2_kernel(const float* __restrict__ vsum, const float* __restrict__ rsum,
                          float* __restrict__ g2, int M)
{
    int gw = (blockIdx.x * blockDim.x + threadIdx.x) >> 5;
    int lane = threadIdx.x & 31;
    if (gw >= M) return;
    float inv = 1.f / rsum[gw];
    float x0 = vsum[(size_t)gw * 64 + lane] * inv;
    float x1 = vsum[(size_t)gw * 64 + 32 + lane] * inv;
    float ss = x0 * x0 + x1 * x1;
    #pragma unroll
    for (int o = 16; o > 0; o >>= 1) ss += __shfl_xor_sync(0xffffffffu, ss, o);
    float d = fmaxf(sqrtf(ss), 1e-12f);
    g2[(size_t)gw * 64 + lane] = 1.f / (1.f + expf(-x0 / d));
    g2[(size_t)gw * 64 + 32 + lane] = 1.f / (1.f + expf(-x1 / d));
}
__global__ void disc_kernel(const float* __restrict__ emb1, const float* __restrict__ emb3,
                            const float* __restrict__ g2, const float* __restrict__ W,
                            const float* __restrict__ bptr, float* __restrict__ ret, int M)
{
    __shared__ float Ws[64][65];
    int tid = threadIdx.x;
    for (int id = tid; id < 4096; id += 256) Ws[id >> 6][id & 63] = W[id];
    __syncthreads();
    int lane = tid & 31;
    int row = blockIdx.x * 8 + (tid >> 5);
    if (row >= M) return;
    float g0 = g2[(size_t)row * 64 + lane];
    float g1 = g2[(size_t)row * 64 + 32 + lane];
    float ulo = 0.f, uhi = 0.f;
    #pragma unroll
    for (int e = 0; e < 64; e++) {
        float ge = (e < 32) ? __shfl_sync(0xffffffffu, g0, e) : __shfl_sync(0xffffffffu, g1, e - 32);
        ulo = fmaf(Ws[lane][e], ge, ulo);
        uhi = fmaf(Ws[lane + 32][e], ge, uhi);
    }
    float s1 = emb1[(size_t)row * 64 + lane] * ulo + emb1[(size_t)row * 64 + 32 + lane] * uhi;
    float s2 = emb3[(size_t)row * 64 + lane] * ulo + emb3[(size_t)row * 64 + 32 + lane] * uhi;
    #pragma unroll
    for (int o = 16; o > 0; o >>= 1) {
        s1 += __shfl_xor_sync(0xffffffffu, s1, o);
        s2 += __shfl_xor_sync(0xffffffffu, s2, o);
    }
    if (lane == 0) {
        float b = bptr[0];
        ret[(size_t)row * 2 + 0] = s1 + b;
        ret[(size_t)row * 2 + 1] = s2 + b;
    }
}

static inline int cdiv(int a, int b) { return (a + b - 1) / b; }

extern "C" void kernel_launch(void* const* d_in, const int* in_sizes, int n_in,
                              void* d_out, int out_size)
{
    const float* feat   = (const float*)d_in[0];
    const float* feat_a = (const float*)d_in[1];
    const float* feat_b = (const float*)d_in[2];
    const int* adj_rows = (const int*)d_in[3];
    const int* adj_cols = (const int*)d_in[4];
    const float* adj_vals = (const float*)d_in[5];
    const float* graphN = (const float*)d_in[6];
    const float* W1 = (const float*)d_in[7];
    const float* W2 = (const float*)d_in[8];
    const float* Wd = (const float*)d_in[9];
    const float* bd = (const float*)d_in[10];
    const float* bn_gamma = (const float*)d_in[11];
    const float* bn_beta  = (const float*)d_in[12];
    const float* bn_mean  = (const float*)d_in[13];
    const float* bn_var   = (const float*)d_in[14];
    const float* Wpi   = (const float*)d_in[15];
    const float* bpi   = (const float*)d_in[16];
    const float* Wdisp = (const float*)d_in[17];
    const float* bdisp = (const float*)d_in[18];
    const float* Wmean = (const float*)d_in[19];
    const float* bmean = (const float*)d_in[20];
    const float* disc_W = (const float*)d_in[21];
    const float* disc_b = (const float*)d_in[22];
    float* out = (float*)d_out;

    #define SYM(T, v, s) T* v; { void* p_; cudaGetSymbolAddress(&p_, s); v = (T*)p_; }
    SYM(float, S, g_S)  SYM(float, H, g_H)  SYM(float, S2, g_S2)
    SYM(float, E1, g_EMB1) SYM(float, E3, g_EMB3) SYM(float, VS, g_VSUM) SYM(float, G2v, g_G2)
    SYM(float, RS, g_RSUM) SYM(float, BA, g_BNA) SYM(float, BB, g_BNB) SYM(float, BCAT, g_BCAT)
    SYM(__nv_bfloat16, Ah, g_Ah) SYM(__nv_bfloat16, Al, g_Al)
    SYM(__nv_bfloat16, W1th, g_W1th) SYM(__nv_bfloat16, W1tl, g_W1tl)
    SYM(__nv_bfloat16, XDh, g_XDh) SYM(__nv_bfloat16, XDl, g_XDl)
    SYM(__nv_bfloat16, Wcth, g_Wcth) SYM(__nv_bfloat16, Wctl, g_Wctl)
    SYM(__nv_bfloat16, Gh, g_Gh) SYM(__nv_bfloat16, E1th, g_E1th) SYM(__nv_bfloat16, E1tl, g_E1tl)
    SYM(__nv_bfloat16, ZNh, g_ZNh) SYM(__nv_bfloat16, ZNl, g_ZNl)
    SYM(int, CNT, g_cnt) SYM(int, START, g_start) SYM(int, POS, g_pos) SYM(int, EIDX, g_eidx)

    const int SM128 = 96 * 1024;
    const int SM64D = 96 * 1024;
    cudaFuncSetAttribute(gemm_mma<128,0,3,0,1>, cudaFuncAttributeMaxDynamicSharedMemorySize, SM128);
    cudaFuncSetAttribute(gemm_mma<128,7,3,0,1>, cudaFuncAttributeMaxDynamicSharedMemorySize, SM128);
    cudaFuncSetAttribute(gemm_mma<128,6,3,0,1>, cudaFuncAttributeMaxDynamicSharedMemorySize, SM128);
    cudaFuncSetAttribute(gemm_mma<64,0,1,1,2>,  cudaFuncAttributeMaxDynamicSharedMemorySize, SM64D);

    const dim3 blk(16, 16);
    const int mt64 = cdiv(NN, 64), mt128 = cdiv(NN, 128);

    // CSR build
    zero_int_kernel<<<cdiv(NN, 256), 256>>>(CNT, NN);
    hist_kernel<<<cdiv(NE, 256), 256>>>(adj_rows, CNT);
    scan_kernel<<<1, 1024>>>(CNT, START, POS, NN);
    scatter_kernel<<<cdiv(NE, 256), 256>>>(adj_rows, POS, EIDX);

    // weight / bias conversions
    conv_transpose<<<(unsigned)(((long long)NP_W1 * KP_FIN + 255) / 256), 256>>>(W1, FIN, HH1, KP_FIN, NP_W1, W1th, W1tl, 0);
    conv_transpose<<<(unsigned)(((long long)NSEG * KP_H1 + 255) / 256), 256>>>(Wpi,   HH1, FIN, KP_H1, NSEG, Wcth,                        Wctl,                        0);
    conv_transpose<<<(unsigned)(((long long)NSEG * KP_H1 + 255) / 256), 256>>>(Wdisp, HH1, FIN, KP_H1, NSEG, Wcth + (size_t)NSEG*KP_H1,   Wctl + (size_t)NSEG*KP_H1,   0);
    conv_transpose<<<(unsigned)(((long long)NSEG * KP_H1 + 255) / 256), 256>>>(Wmean, HH1, FIN, KP_H1, NSEG, Wcth + (size_t)2*NSEG*KP_H1, Wctl + (size_t)2*NSEG*KP_H1, 0);
    biascat_kernel<<<cdiv(NP_DEC, 256), 256>>>(bpi, bdisp, bmean, BCAT);
    bnprep_kernel<<<cdiv(HH1, 256), 256>>>(bn_gamma, bn_beta, bn_mean, bn_var, bd, BA, BB);
    conv_rows<<<NN, 256>>>(graphN, NN, KP_N, Gh, nullptr, RS);

    // ---- encodes (per-encode, L2-friendly) ----
    const float* xs[3] = {feat, feat_a, feat_b};
    float* Eo[3] = {E1, nullptr, E3};
    for (int s = 0; s < 3; s++) {
        float* z = out + Z1_OFF + (long long)s * 640000LL;
        conv_rows<<<NN, 256>>>(xs[s], FIN, KP_FIN, Ah, Al, nullptr);
        gemm_mma<128,0,3,0,1><<<dim3(NP_W1 / 128, mt128), 256, SM128>>>(
            Ah, Al, KP_FIN, W1th, W1tl, KP_FIN, NP_W1, S, HH1, NN, HH1, KP_FIN, nullptr);
        agg_csr_500<<<NN, 256>>>(START, EIDX, adj_cols, adj_vals, S, H);
        sgemm0_kernel<<<dim3(1, mt64), blk>>>(H, W2, S2, NN, HH2, HH1);
        agg_csr_64<<<cdiv(NN, 4), 256>>>(START, EIDX, adj_cols, adj_vals, S2, z, Eo[s]);
    }
    float* z1 = out + Z1_OFF;

    // ---- ZINB decoder: fused single GEMM (N = 9216) ----
    sgemm_xd_kernel<<<dim3(cdiv(HH1, 64), mt64), blk>>>(z1, Wd, XDh, XDl, NN, HH1, HH2, BA, BB);
    gemm_mma<128,7,3,0,1><<<dim3(NP_DEC / 128, mt128), 256, SM128>>>(
        XDh, XDl, KP_H1, Wcth, Wctl, KP_H1, NP_DEC, out + PI_OFF, FIN, NN, NP_DEC, KP_H1, BCAT);

    // ---- rec_adj = poly-sigmoid(zn @ zn^T) ----
    znconv_kernel<<<cdiv(NN * 32, 256), 256>>>(z1, ZNh, ZNl, NN);
    gemm_mma<128,6,3,0,1><<<dim3(cdiv(NN, 128), mt128), 256, SM128>>>(
        ZNh, ZNl, 64, ZNh, ZNl, 64, NN, out + REC_OFF, NN, NN, NN, 64, nullptr);

    // ---- readout: single pass (dual-B) + split-K=2 ----
    conv_transpose<<<(unsigned)(((long long)64 * KP_N + 255) / 256), 256>>>(z1, NN, HH2, KP_N, 64, E1th, E1tl, 1);
    zero_kernel<<<cdiv(NN * HH2 / 4, 256), 256>>>((float4*)VS, (long long)NN * HH2 / 4);
    gemm_mma<64,0,1,1,2><<<dim3(1, mt128, 2), 256, SM64D>>>(
        Gh, nullptr, KP_N, E1th, E1tl, KP_N, 64, VS, HH2, NN, HH2, KP_N, nullptr);
    g2_kernel<<<cdiv(NN * 32, 256), 256>>>(VS, RS, G2v, NN);
    disc_kernel<<<cdiv(NN, 8), 256>>>(E1, E3, G2v, disc_W, disc_b, out + RET_OFF, NN);
}